// round 15
// baseline (speedup 1.0000x reference)
#include <cuda_runtime.h>
#include <cuda_bf16.h>
#include <cstdint>

// ---------------------------------------------------------------------------
// RelGAT, fully restructured (round 15):
//   score_e = <g[dst], h[src] + ef_e> + c[dst],   g = h@W1^T,  c = <h, b1>
//   q_d     = sum_e w_e (h[src]+ef_e),  den_d = sum_e w_e,   w_e = exp(score)
//   out     = lrelu( h@W2 + b2 + b1 + (q@W1)/den )     (deg==0 rows -> fixup)
// Per layer: ONE plain GEMM (g), agg (single accumulator), ONE fused GEMM
// (q@W1 scaled in-register, then += h@W2, fused bias+lrelu epilogue).
// GEMM operands pre-split bf16 hi/lo in GMEM; fills are pure cp.async.
// ---------------------------------------------------------------------------

namespace {
constexpr int    NN  = 50000;
constexpr int    NE  = 600000;
constexpr size_t ND  = (size_t)NN * 128;
constexpr float  NEG_SLOPE = 0.22916666666666666f;

constexpr size_t AL16(size_t x) { return (x + 3) & ~(size_t)3; }  // 16B align

// scratch layout (floats); every sub-buffer 16B aligned
constexpr size_t O_G    = 0;
constexpr size_t O_H1   = 1 * ND;
constexpr size_t O_HHI  = 2 * ND;
constexpr size_t O_HLO  = 2 * ND + ND / 2;
constexpr size_t O_QHI  = 3 * ND;
constexpr size_t O_QLO  = 3 * ND + ND / 2;
constexpr size_t O_DEN    = 4 * ND;
constexpr size_t O_DEG    = AL16(O_DEN + NN);
constexpr size_t O_ROWPTR = AL16(O_DEG + NN);
constexpr size_t O_WPOS   = AL16(O_ROWPTR + NN + 1);
constexpr size_t O_CSRS   = AL16(O_WPOS + NN);
constexpr size_t O_CSRE   = AL16(O_CSRS + NE);
constexpr size_t O_WSP    = AL16(O_CSRE + NE);   // 4 x 16384 bf16
constexpr size_t SCRATCH  = O_WSP + 32768 + 64;

// K-chunked GEMM smem (bytes), chunk K=64:
constexpr int LDA  = 144;
constexpr int LDBT = 272;
constexpr int LDBN = 144;
constexpr int A_HI = 0;
constexpr int A_LO = A_HI + 128 * LDA;       // 18432
constexpr int B_HI = A_LO + 128 * LDA;       // 36864
constexpr int B_LO = B_HI + 128 * LDBN;      // 55296
constexpr int GEMM_SMEM = B_LO + 128 * LDBN; // 73728 -> 2 CTAs/SM
}  // namespace

__device__ __align__(256) float g_scratch[SCRATCH];

// ---------------------------------------------------------------------------
// helpers
// ---------------------------------------------------------------------------
__device__ __forceinline__ uint32_t smem_u32(const void* p) {
    uint32_t a;
    asm("{ .reg .u64 t; cvta.to.shared.u64 t, %1; cvt.u32.u64 %0, t; }" : "=r"(a) : "l"(p));
    return a;
}
__device__ __forceinline__ void cpasync16(uint32_t saddr, const void* g, uint32_t srcsz) {
    asm volatile("cp.async.cg.shared.global [%0], [%1], 16, %2;"
                 :: "r"(saddr), "l"(g), "r"(srcsz) : "memory");
}
__device__ __forceinline__ void ldsm_x4(uint32_t* r, uint32_t addr) {
    asm volatile("ldmatrix.sync.aligned.m8n8.x4.shared.b16 {%0,%1,%2,%3}, [%4];"
                 : "=r"(r[0]), "=r"(r[1]), "=r"(r[2]), "=r"(r[3]) : "r"(addr));
}
__device__ __forceinline__ void ldsm_x4t(uint32_t* r, uint32_t addr) {
    asm volatile("ldmatrix.sync.aligned.m8n8.x4.trans.shared.b16 {%0,%1,%2,%3}, [%4];"
                 : "=r"(r[0]), "=r"(r[1]), "=r"(r[2]), "=r"(r[3]) : "r"(addr));
}
__device__ __forceinline__ void mma_bf16(float* d, const uint32_t* a, const uint32_t* b) {
    asm volatile("mma.sync.aligned.m16n8k16.row.col.f32.bf16.bf16.f32 "
                 "{%0,%1,%2,%3}, {%4,%5,%6,%7}, {%8,%9}, {%0,%1,%2,%3};"
                 : "+f"(d[0]), "+f"(d[1]), "+f"(d[2]), "+f"(d[3])
                 : "r"(a[0]), "r"(a[1]), "r"(a[2]), "r"(a[3]), "r"(b[0]), "r"(b[1]));
}
__device__ __forceinline__ float lrelu(float v) { return v >= 0.f ? v : v * NEG_SLOPE; }

__device__ __forceinline__ void split2(float x, float y,
                                       __nv_bfloat162& hi, __nv_bfloat162& lo) {
    hi = __float22bfloat162_rn(make_float2(x, y));
    float2 f = __bfloat1622float2(hi);
    lo = __float22bfloat162_rn(make_float2(x - f.x, y - f.y));
}

// ---------------------------------------------------------------------------
// GEMM building blocks (chunk K=64, pre-split bf16 hi/lo operands)
// ---------------------------------------------------------------------------
__device__ __forceinline__ void fill_A(uint32_t sb, int tid,
                                       const __nv_bfloat16* Ahi, const __nv_bfloat16* Alo,
                                       int row0, int c, int M)
{
    const int r  = tid >> 1;
    const int j0 = (tid & 1) * 4;
    const bool valid = (row0 + r) < M;
    const uint32_t ssz = valid ? 16u : 0u;
    const size_t grow = valid ? (size_t)(row0 + r) : 0;
    const char* gH = (const char*)Ahi + grow * 256 + c * 128 + j0 * 16;
    const char* gL = (const char*)Alo + grow * 256 + c * 128 + j0 * 16;
    const uint32_t sH = sb + A_HI + r * LDA + j0 * 16;
    const uint32_t sL = sb + A_LO + r * LDA + j0 * 16;
#pragma unroll
    for (int i = 0; i < 4; ++i) {
        cpasync16(sH + i * 16, gH + i * 16, ssz);
        cpasync16(sL + i * 16, gL + i * 16, ssz);
    }
}
// W stored [k][n]: 64 k-rows per chunk, 256B/row  (C = A@W)
__device__ __forceinline__ void fill_Bt(uint32_t sb, int tid,
                                        const __nv_bfloat16* Bhi, const __nv_bfloat16* Blo,
                                        int c)
{
    const int kr = tid >> 2;
    const int j0 = (tid & 3) * 4;
    const char* gH = (const char*)Bhi + (size_t)(c * 64 + kr) * 256 + j0 * 16;
    const char* gL = (const char*)Blo + (size_t)(c * 64 + kr) * 256 + j0 * 16;
    const uint32_t sH = sb + B_HI + kr * LDBT + j0 * 16;
    const uint32_t sL = sb + B_LO + kr * LDBT + j0 * 16;
#pragma unroll
    for (int i = 0; i < 4; ++i) {
        cpasync16(sH + i * 16, gH + i * 16, 16u);
        cpasync16(sL + i * 16, gL + i * 16, 16u);
    }
}
// W stored [n][k]: 128 n-rows, chunk cols (C = A@W^T)
__device__ __forceinline__ void fill_Bn(uint32_t sb, int tid,
                                        const __nv_bfloat16* Bhi, const __nv_bfloat16* Blo,
                                        int c)
{
    const int nr = tid >> 1;
    const int j0 = (tid & 1) * 4;
    const char* gH = (const char*)Bhi + (size_t)nr * 256 + c * 128 + j0 * 16;
    const char* gL = (const char*)Blo + (size_t)nr * 256 + c * 128 + j0 * 16;
    const uint32_t sH = sb + B_HI + nr * LDBN + j0 * 16;
    const uint32_t sL = sb + B_LO + nr * LDBN + j0 * 16;
#pragma unroll
    for (int i = 0; i < 4; ++i) {
        cpasync16(sH + i * 16, gH + i * 16, 16u);
        cpasync16(sL + i * 16, gL + i * 16, 16u);
    }
}
#define CP_COMMIT_WAIT() do { \
    asm volatile("cp.async.commit_group;" ::: "memory"); \
    asm volatile("cp.async.wait_group 0;" ::: "memory"); } while (0)

// 3 emulation groups (hh, hl, lh) x 4 k16-steps over one K=64 chunk
__device__ __forceinline__ void mma_chunk(uint32_t sb, uint32_t a_off,
                                          uint32_t bt_off, uint32_t bn_off,
                                          int wkn, float acc[2][8][4])
{
#pragma unroll
    for (int g = 0; g < 3; ++g) {
        const uint32_t abase = sb + (g == 2 ? A_LO : A_HI);
        const uint32_t bbase = sb + (g == 1 ? B_LO : B_HI);
#pragma unroll
        for (int kk = 0; kk < 4; ++kk) {
            uint32_t a0[4], a1[4];
            ldsm_x4(a0, abase + a_off + kk * 32);
            ldsm_x4(a1, abase + a_off + 16 * LDA + kk * 32);
#pragma unroll
            for (int p = 0; p < 4; ++p) {
                uint32_t b4[4];
                if (wkn)
                    ldsm_x4t(b4, bbase + bt_off + (uint32_t)(kk * 16 * LDBT + p * 32));
                else
                    ldsm_x4(b4, bbase + bn_off + (uint32_t)(p * 16 * LDBN + kk * 32));
                mma_bf16(acc[0][2 * p],     a0, b4);
                mma_bf16(acc[0][2 * p + 1], a0, b4 + 2);
                mma_bf16(acc[1][2 * p],     a1, b4);
                mma_bf16(acc[1][2 * p + 1], a1, b4 + 2);
            }
        }
    }
}

// ---------------------------------------------------------------------------
// plain GEMM: C[M,128] = A @ W^T  (wkn=0 path; used for g = h@W1^T)
// ---------------------------------------------------------------------------
__global__ __launch_bounds__(256, 2)
void tc_gemm_w(const __nv_bfloat16* __restrict__ Ahi, const __nv_bfloat16* __restrict__ Alo,
               const __nv_bfloat16* __restrict__ Bhi, const __nv_bfloat16* __restrict__ Blo,
               float* __restrict__ C, int M)
{
    extern __shared__ char smem[];
    const uint32_t sb = smem_u32(smem);
    const int tid = threadIdx.x, wid = tid >> 5, lane = tid & 31;
    const int row0 = blockIdx.x * 128;
    const int mw = (wid & 3) * 32, nw = (wid >> 2) * 64;

    const uint32_t a_off  = (uint32_t)((mw + (lane & 15)) * LDA + ((lane >> 4) << 4));
    const uint32_t bt_off = (uint32_t)((((lane >> 3) & 1) * 8 + (lane & 7)) * LDBT
                                       + (nw + ((lane >> 4) << 3)) * 2);
    const uint32_t bn_off = (uint32_t)((nw + ((lane >> 4) << 3) + (lane & 7)) * LDBN
                                       + ((lane >> 3) & 1) * 16);

    float acc[2][8][4];
#pragma unroll
    for (int mt = 0; mt < 2; ++mt)
#pragma unroll
        for (int nt = 0; nt < 8; ++nt)
#pragma unroll
            for (int j = 0; j < 4; ++j) acc[mt][nt][j] = 0.f;

#pragma unroll
    for (int c = 0; c < 2; ++c) {
        __syncthreads();
        fill_A(sb, tid, Ahi, Alo, row0, c, M);
        fill_Bn(sb, tid, Bhi, Blo, c);
        CP_COMMIT_WAIT();
        __syncthreads();
        mma_chunk(sb, a_off, bt_off, bn_off, 0, acc);
    }

    const int rq = lane >> 2, c2 = (lane & 3) * 2;
#pragma unroll
    for (int mt = 0; mt < 2; ++mt) {
        const int r0 = row0 + mw + mt * 16 + rq;
#pragma unroll
        for (int nt = 0; nt < 8; ++nt) {
            const int col = nw + nt * 8 + c2;
            if (r0 < M)
                *reinterpret_cast<float2*>(C + (size_t)r0 * 128 + col) =
                    make_float2(acc[mt][nt][0], acc[mt][nt][1]);
            if (r0 + 8 < M)
                *reinterpret_cast<float2*>(C + (size_t)(r0 + 8) * 128 + col) =
                    make_float2(acc[mt][nt][2], acc[mt][nt][3]);
        }
    }
}

// ---------------------------------------------------------------------------
// fused finalize GEMM:
//   acc = q@W1; acc *= 1/max(den,1e-30); acc += h@W2;
//   out = lrelu(acc + b1 + b2); optional hi/lo emit (next layer's A).
// ---------------------------------------------------------------------------
__global__ __launch_bounds__(256, 2)
void tc_gemm_fin2(const __nv_bfloat16* __restrict__ Qhi, const __nv_bfloat16* __restrict__ Qlo,
                  const __nv_bfloat16* __restrict__ Hhi, const __nv_bfloat16* __restrict__ Hlo,
                  const __nv_bfloat16* __restrict__ w1h, const __nv_bfloat16* __restrict__ w1l,
                  const __nv_bfloat16* __restrict__ w2h, const __nv_bfloat16* __restrict__ w2l,
                  const float* __restrict__ b1, const float* __restrict__ b2,
                  const float* __restrict__ denom, float* __restrict__ out,
                  __nv_bfloat16* __restrict__ outhi, __nv_bfloat16* __restrict__ outlo, int M)
{
    extern __shared__ char smem[];
    const uint32_t sb = smem_u32(smem);
    const int tid = threadIdx.x, wid = tid >> 5, lane = tid & 31;
    const int row0 = blockIdx.x * 128;
    const int mw = (wid & 3) * 32, nw = (wid >> 2) * 64;

    const uint32_t a_off  = (uint32_t)((mw + (lane & 15)) * LDA + ((lane >> 4) << 4));
    const uint32_t bt_off = (uint32_t)((((lane >> 3) & 1) * 8 + (lane & 7)) * LDBT
                                       + (nw + ((lane >> 4) << 3)) * 2);

    float acc[2][8][4];
#pragma unroll
    for (int mt = 0; mt < 2; ++mt)
#pragma unroll
        for (int nt = 0; nt < 8; ++nt)
#pragma unroll
            for (int j = 0; j < 4; ++j) acc[mt][nt][j] = 0.f;

    // pass 1: acc = q @ W1
#pragma unroll
    for (int c = 0; c < 2; ++c) {
        __syncthreads();
        fill_A(sb, tid, Qhi, Qlo, row0, c, M);
        fill_Bt(sb, tid, w1h, w1l, c);
        CP_COMMIT_WAIT();
        __syncthreads();
        mma_chunk(sb, a_off, bt_off, 0, 1, acc);
    }

    // scale by 1/max(den,1e-30)
    const int rq = lane >> 2, c2 = (lane & 3) * 2;
#pragma unroll
    for (int mt = 0; mt < 2; ++mt) {
        const int rA = row0 + mw + mt * 16 + rq;
        const int rB = rA + 8;
        const float invA = (rA < M) ? 1.0f / fmaxf(__ldg(denom + rA), 1e-30f) : 0.f;
        const float invB = (rB < M) ? 1.0f / fmaxf(__ldg(denom + rB), 1e-30f) : 0.f;
#pragma unroll
        for (int nt = 0; nt < 8; ++nt) {
            acc[mt][nt][0] *= invA; acc[mt][nt][1] *= invA;
            acc[mt][nt][2] *= invB; acc[mt][nt][3] *= invB;
        }
    }

    // pass 2: acc += h @ W2
#pragma unroll
    for (int c = 0; c < 2; ++c) {
        __syncthreads();
        fill_A(sb, tid, Hhi, Hlo, row0, c, M);
        fill_Bt(sb, tid, w2h, w2l, c);
        CP_COMMIT_WAIT();
        __syncthreads();
        mma_chunk(sb, a_off, bt_off, 0, 1, acc);
    }

    // epilogue: out = lrelu(acc + b1 + b2)
#pragma unroll
    for (int mt = 0; mt < 2; ++mt) {
        const int rA = row0 + mw + mt * 16 + rq;
        const int rB = rA + 8;
#pragma unroll
        for (int nt = 0; nt < 8; ++nt) {
            const int col = nw + nt * 8 + c2;
            const float bx = __ldg(b1 + col) + __ldg(b2 + col);
            const float by = __ldg(b1 + col + 1) + __ldg(b2 + col + 1);
            if (rA < M) {
                float vx = lrelu(acc[mt][nt][0] + bx);
                float vy = lrelu(acc[mt][nt][1] + by);
                *reinterpret_cast<float2*>(out + (size_t)rA * 128 + col) = make_float2(vx, vy);
                if (outhi) {
                    __nv_bfloat162 hi, lo;
                    split2(vx, vy, hi, lo);
                    *reinterpret_cast<__nv_bfloat162*>(outhi + (size_t)rA * 128 + col) = hi;
                    *reinterpret_cast<__nv_bfloat162*>(outlo + (size_t)rA * 128 + col) = lo;
                }
            }
            if (rB < M) {
                float vx = lrelu(acc[mt][nt][2] + bx);
                float vy = lrelu(acc[mt][nt][3] + by);
                *reinterpret_cast<float2*>(out + (size_t)rB * 128 + col) = make_float2(vx, vy);
                if (outhi) {
                    __nv_bfloat162 hi, lo;
                    split2(vx, vy, hi, lo);
                    *reinterpret_cast<__nv_bfloat162*>(outhi + (size_t)rB * 128 + col) = hi;
                    *reinterpret_cast<__nv_bfloat162*>(outlo + (size_t)rB * 128 + col) = lo;
                }
            }
        }
    }
}

// ---------------------------------------------------------------------------
// split kernels
// ---------------------------------------------------------------------------
__global__ void hsplit_kernel(const float* __restrict__ x,
                              __nv_bfloat16* __restrict__ hi, __nv_bfloat16* __restrict__ lo)
{
    size_t i = ((size_t)blockIdx.x * blockDim.x + threadIdx.x) * 2;
    if (i >= ND) return;
    float2 v = *reinterpret_cast<const float2*>(x + i);
    __nv_bfloat162 h2, l2;
    split2(v.x, v.y, h2, l2);
    *reinterpret_cast<__nv_bfloat162*>(hi + i) = h2;
    *reinterpret_cast<__nv_bfloat162*>(lo + i) = l2;
}

__global__ void wsplit_kernel(const float* __restrict__ W1, const float* __restrict__ W2,
                              __nv_bfloat16* __restrict__ w1h, __nv_bfloat16* __restrict__ w1l,
                              __nv_bfloat16* __restrict__ w2h, __nv_bfloat16* __restrict__ w2l)
{
    int i = (blockIdx.x * blockDim.x + threadIdx.x) * 2;
    if (i >= 16384) return;
    float2 v = *reinterpret_cast<const float2*>(W1 + i);
    __nv_bfloat162 h2, l2;
    split2(v.x, v.y, h2, l2);
    *reinterpret_cast<__nv_bfloat162*>(w1h + i) = h2;
    *reinterpret_cast<__nv_bfloat162*>(w1l + i) = l2;
    v = *reinterpret_cast<const float2*>(W2 + i);
    split2(v.x, v.y, h2, l2);
    *reinterpret_cast<__nv_bfloat162*>(w2h + i) = h2;
    *reinterpret_cast<__nv_bfloat162*>(w2l + i) = l2;
}

// ---------------------------------------------------------------------------
// CSR build (once; graph shared by both layers)
// ---------------------------------------------------------------------------
__global__ void zero_int_kernel(int* p, int n)
{
    int i = blockIdx.x * blockDim.x + threadIdx.x;
    if (i < n) p[i] = 0;
}

__global__ void deg_kernel(const int* __restrict__ dst, int* __restrict__ deg)
{
    int e = blockIdx.x * blockDim.x + threadIdx.x;
    if (e < NE) atomicAdd(deg + dst[e], 1);
}

__global__ __launch_bounds__(1024) void scan_kernel(const int* __restrict__ deg,
                                                    int* __restrict__ rowptr,
                                                    int* __restrict__ wpos)
{
    __shared__ int warpsum[32];
    __shared__ int carry_s;
    const int tid = threadIdx.x, lane = tid & 31, wid = tid >> 5;
    if (tid == 0) { carry_s = 0; rowptr[0] = 0; }
    __syncthreads();
    for (int base = 0; base < NN; base += 1024) {
        int i = base + tid;
        int v = (i < NN) ? deg[i] : 0;
        int x = v;
#pragma unroll
        for (int o = 1; o < 32; o <<= 1) {
            int y = __shfl_up_sync(0xffffffffu, x, o);
            if (lane >= o) x += y;
        }
        if (lane == 31) warpsum[wid] = x;
        __syncthreads();
        if (wid == 0) {
            int s = warpsum[lane];
#pragma unroll
            for (int o = 1; o < 32; o <<= 1) {
                int y = __shfl_up_sync(0xffffffffu, s, o);
                if (lane >= o) s += y;
            }
            warpsum[lane] = s;
        }
        __syncthreads();
        int incl = x + (wid > 0 ? warpsum[wid - 1] : 0) + carry_s;
        if (i < NN) { rowptr[i + 1] = incl; wpos[i] = incl - v; }
        __syncthreads();
        if (tid == 1023) carry_s = incl;
        __syncthreads();
    }
}

__global__ void csr_scatter(const int* __restrict__ src, const int* __restrict__ dst,
                            int* __restrict__ wpos,
                            int* __restrict__ csr_src, int* __restrict__ csr_e)
{
    int e = blockIdx.x * blockDim.x + threadIdx.x;
    if (e >= NE) return;
    int d = __ldg(dst + e);
    int p = atomicAdd(wpos + d, 1);
    csr_src[p] = __ldg(src + e);
    csr_e[p]   = e;
}

// ---------------------------------------------------------------------------
// aggregation: one warp per dst node.
//   c = <h[d], b1>;  per edge: sum = h[s]+ef;  p = <g[d], sum> (+c);
//   w = exp(p);  q += w*sum;  den += w.   q emitted as bf16 hi/lo.
// ---------------------------------------------------------------------------
__global__ __launch_bounds__(256) void agg_kernel(
    const float* __restrict__ h, const float* __restrict__ g,
    const float* __restrict__ ef, const float* __restrict__ b1,
    const int* __restrict__ rowptr, const int* __restrict__ csr_src,
    const int* __restrict__ csr_e,
    float* __restrict__ denom,
    __nv_bfloat16* __restrict__ qhi, __nv_bfloat16* __restrict__ qlo)
{
    const int n = blockIdx.x * 8 + (threadIdx.x >> 5);
    if (n >= NN) return;
    const int lane = threadIdx.x & 31;
    const int beg = __ldg(rowptr + n), end = __ldg(rowptr + n + 1);

    float4 aq = make_float4(0.f, 0.f, 0.f, 0.f);
    float den = 0.f;

    if (beg < end) {
        const float4 gd  = __ldg(reinterpret_cast<const float4*>(g)  + n * 32 + lane);
        const float4 hd  = __ldg(reinterpret_cast<const float4*>(h)  + n * 32 + lane);
        const float4 b1v = __ldg(reinterpret_cast<const float4*>(b1) + lane);

        // c = <h[d], b1>  (node constant, reduced once)
        float cp = hd.x * b1v.x + hd.y * b1v.y + hd.z * b1v.z + hd.w * b1v.w;
#pragma unroll
        for (int o = 16; o > 0; o >>= 1) cp += __shfl_xor_sync(0xffffffffu, cp, o);

        int i = beg;
        for (; i + 1 < end; i += 2) {
            const int s0 = __ldg(csr_src + i),     e0 = __ldg(csr_e + i);
            const int s1 = __ldg(csr_src + i + 1), e1 = __ldg(csr_e + i + 1);
            const float4 hs0 = __ldg(reinterpret_cast<const float4*>(h)  + (size_t)s0 * 32 + lane);
            const float4 ev0 = __ldg(reinterpret_cast<const float4*>(ef) + (size_t)e0 * 32 + lane);
            const float4 hs1 = __ldg(reinterpret_cast<const float4*>(h)  + (size_t)s1 * 32 + lane);
            const float4 ev1 = __ldg(reinterpret_cast<const float4*>(ef) + (size_t)e1 * 32 + lane);

            float4 u0 = make_float4(hs0.x + ev0.x, hs0.y + ev0.y, hs0.z + ev0.z, hs0.w + ev0.w);
            float4 u1 = make_float4(hs1.x + ev1.x, hs1.y + ev1.y, hs1.z + ev1.z, hs1.w + ev1.w);

            float p0 = gd.x * u0.x + gd.y * u0.y + gd.z * u0.z + gd.w * u0.w;
            float p1 = gd.x * u1.x + gd.y * u1.y + gd.z * u1.z + gd.w * u1.w;
#pragma unroll
            for (int o = 16; o > 0; o >>= 1) {
                p0 += __shfl_xor_sync(0xffffffffu, p0, o);
                p1 += __shfl_xor_sync(0xffffffffu, p1, o);
            }
            const float w0 = __expf(p0 + cp), w1 = __expf(p1 + cp);
            aq.x += w0 * u0.x + w1 * u1.x;  aq.y += w0 * u0.y + w1 * u1.y;
            aq.z += w0 * u0.z + w1 * u1.z;  aq.w += w0 * u0.w + w1 * u1.w;
            den += w0 + w1;
        }
        if (i < end) {
            const int s0 = __ldg(csr_src + i), e0 = __ldg(csr_e + i);
            const float4 hs0 = __ldg(reinterpret_cast<const float4*>(h)  + (size_t)s0 * 32 + lane);
            const float4 ev0 = __ldg(reinterpret_cast<const float4*>(ef) + (size_t)e0 * 32 + lane);
            float4 u0 = make_float4(hs0.x + ev0.x, hs0.y + ev0.y, hs0.z + ev0.z, hs0.w + ev0.w);
            float p0 = gd.x * u0.x + gd.y * u0.y + gd.z * u0.z + gd.w * u0.w;
#pragma unroll
            for (int o = 16; o > 0; o >>= 1) p0 += __shfl_xor_sync(0xffffffffu, p0, o);
            const float w0 = __expf(p0 + cp);
            aq.x += w0 * u0.x; aq.y += w0 * u0.y; aq.z += w0 * u0.z; aq.w += w0 * u0.w;
            den += w0;
        }
    }

    {
        const size_t idx = (size_t)n * 128 + lane * 4;
        __nv_bfloat162 h01, l01, h23, l23;
        split2(aq.x, aq.y, h01, l01);
        split2(aq.z, aq.w, h23, l23);
        *reinterpret_cast<__nv_bfloat162*>(qhi + idx)     = h01;
        *reinterpret_cast<__nv_bfloat162*>(qhi + idx + 2) = h23;
        *reinterpret_cast<__nv_bfloat162*>(qlo + idx)     = l01;
        *reinterpret_cast<__nv_bfloat162*>(qlo + idx + 2) = l23;
    }
    if (lane == 0) denom[n] = den;
}

// ---------------------------------------------------------------------------
// fixup: for the rare deg==0 nodes, out = lrelu(h@W3 + b3).  warp/node.
// ---------------------------------------------------------------------------
__global__ __launch_bounds__(256) void fixup_iso(
    const float* __restrict__ h, const float* __restrict__ W3,
    const float* __restrict__ b3, const int* __restrict__ rowptr,
    float* __restrict__ out,
    __nv_bfloat16* __restrict__ outhi, __nv_bfloat16* __restrict__ outlo)
{
    int n = blockIdx.x * 8 + (threadIdx.x >> 5);
    if (n >= NN) return;
    if (__ldg(rowptr + n + 1) != __ldg(rowptr + n)) return;
    int lane = threadIdx.x & 31;
    int c0 = lane * 4;

    float acc0 = __ldg(b3 + c0), acc1 = __ldg(b3 + c0 + 1);
    float acc2 = __ldg(b3 + c0 + 2), acc3 = __ldg(b3 + c0 + 3);
    for (int k = 0; k < 128; ++k) {
        float hv = __ldg(h + (size_t)n * 128 + k);
        const float* wr = W3 + (size_t)k * 128 + c0;
        acc0 += hv * __ldg(wr);
        acc1 += hv * __ldg(wr + 1);
        acc2 += hv * __ldg(wr + 2);
        acc3 += hv * __ldg(wr + 3);
    }
    float4 r = make_float4(lrelu(acc0), lrelu(acc1), lrelu(acc2), lrelu(acc3));
    *reinterpret_cast<float4*>(out + (size_t)n * 128 + c0) = r;
    if (outhi) {
        __nv_bfloat162 h01, l01, h23, l23;
        split2(r.x, r.y, h01, l01);
        split2(r.z, r.w, h23, l23);
        const size_t idx = (size_t)n * 128 + c0;
        *reinterpret_cast<__nv_bfloat162*>(outhi + idx)     = h01;
        *reinterpret_cast<__nv_bfloat162*>(outhi + idx + 2) = h23;
        *reinterpret_cast<__nv_bfloat162*>(outlo + idx)     = l01;
        *reinterpret_cast<__nv_bfloat162*>(outlo + idx + 2) = l23;
    }
}

// ---------------------------------------------------------------------------
// launch
// ---------------------------------------------------------------------------
extern "C" void kernel_launch(void* const* d_in, const int* in_sizes, int n_in,
                              void* d_out, int out_size)
{
    const float* node = (const float*)d_in[0];
    const float* ef   = (const float*)d_in[1];
    const int*   src  = (const int*)d_in[2];
    const int*   dst  = (const int*)d_in[3];
    const float* W1[2] = {(const float*)d_in[4],  (const float*)d_in[10]};
    const float* B1[2] = {(const float*)d_in[5],  (const float*)d_in[11]};
    const float* W2[2] = {(const float*)d_in[6],  (const float*)d_in[12]};
    const float* B2[2] = {(const float*)d_in[7],  (const float*)d_in[13]};
    const float* W3[2] = {(const float*)d_in[8],  (const float*)d_in[14]};
    const float* B3[2] = {(const float*)d_in[9],  (const float*)d_in[15]};

    float* base = nullptr;
    cudaGetSymbolAddress((void**)&base, g_scratch);

    float* g      = base + O_G;
    float* h1     = base + O_H1;
    __nv_bfloat16* hhi  = (__nv_bfloat16*)(base + O_HHI);
    __nv_bfloat16* hlo  = (__nv_bfloat16*)(base + O_HLO);
    __nv_bfloat16* qhi  = (__nv_bfloat16*)(base + O_QHI);
    __nv_bfloat16* qlo  = (__nv_bfloat16*)(base + O_QLO);
    float* denom  = base + O_DEN;
    int*   deg    = (int*)(base + O_DEG);
    int*   rowptr = (int*)(base + O_ROWPTR);
    int*   wpos   = (int*)(base + O_WPOS);
    int*   csrs   = (int*)(base + O_CSRS);
    int*   csre   = (int*)(base + O_CSRE);
    __nv_bfloat16* w1h = (__nv_bfloat16*)(base + O_WSP);
    __nv_bfloat16* w1l = w1h + 16384;
    __nv_bfloat16* w2h = w1l + 16384;
    __nv_bfloat16* w2l = w2h + 16384;

    cudaFuncSetAttribute(tc_gemm_w,    cudaFuncAttributeMaxDynamicSharedMemorySize, GEMM_SMEM);
    cudaFuncSetAttribute(tc_gemm_fin2, cudaFuncAttributeMaxDynamicSharedMemorySize, GEMM_SMEM);

    // ---- CSR build (once) ----
    zero_int_kernel<<<(NN + 255) / 256, 256>>>(deg, NN);
    deg_kernel<<<(NE + 255) / 256, 256>>>(dst, deg);
    scan_kernel<<<1, 1024>>>(deg, rowptr, wpos);
    csr_scatter<<<(NE + 255) / 256, 256>>>(src, dst, wpos, csrs, csre);

    // ---- split layer-0 A operand (node feats) ----
    hsplit_kernel<<<(int)((ND / 2 + 255) / 256), 256>>>(node, hhi, hlo);

    const int gemmGrid = (NN + 127) / 128;   // 391
    const int nodeGrid = (NN + 7) / 8;       // 6250

    const float* h = node;
    float* out_l[2] = {h1, (float*)d_out};

    for (int l = 0; l < 2; ++l) {
        wsplit_kernel<<<32, 256>>>(W1[l], W2[l], w1h, w1l, w2h, w2l);

        // g = h @ W1^T
        tc_gemm_w<<<gemmGrid, 256, GEMM_SMEM>>>(hhi, hlo, w1h, w1l, g, NN);

        agg_kernel<<<nodeGrid, 256>>>(h, g, ef, B1[l], rowptr, csrs, csre,
                                      denom, qhi, qlo);

        // out = lrelu( (q@W1)/den + h@W2 + b1 + b2 ); layer0 also emits hi/lo
        tc_gemm_fin2<<<gemmGrid, 256, GEMM_SMEM>>>(
            qhi, qlo, hhi, hlo, w1h, w1l, w2h, w2l,
            B1[l], B2[l], denom, out_l[l],
            (l == 0) ? hhi : nullptr, (l == 0) ? hlo : nullptr, NN);

        fixup_iso<<<nodeGrid, 256>>>(h, W3[l], B3[l], rowptr, out_l[l],
                                     (l == 0) ? hhi : nullptr,
                                     (l == 0) ? hlo : nullptr);

        h = h1;
    }
}

// round 16
// speedup vs baseline: 1.0882x; 1.0882x over previous
#include <cuda_runtime.h>
#include <cuda_bf16.h>
#include <cstdint>

// ---------------------------------------------------------------------------
// RelGAT restructured (R16 = proven R14 + hoisted weight splits + 4-way agg):
//   score_e = <h[dst], hW1[src]> + <g[dst], efeat_e>,  g = h@W1^T, hW1 = h@W1+b1
//   neigh_d = ( sum w_e hW1[src] + (sum w_e efeat_e)@W1 ) / denom
// GEMM operands pre-split to bf16 hi/lo in GMEM; fills are pure cp.async;
// K-chunked 2-CTA/SM GEMM; batched gridDim.y=3; fused finalize epilogue;
// dst-CSR agg (4-way interleave); softmax rescale; iso fixup.
// ---------------------------------------------------------------------------

namespace {
constexpr int    NN  = 50000;
constexpr int    NE  = 600000;
constexpr size_t ND  = (size_t)NN * 128;
constexpr float  NEG_SLOPE = 0.22916666666666666f;

constexpr size_t AL16(size_t x) { return (x + 3) & ~(size_t)3; }  // 16B align

// scratch layout in float units — every sub-buffer 16B aligned
constexpr size_t O_HW1  = 0;
constexpr size_t O_G    = 1 * ND;
constexpr size_t O_SELF = 2 * ND;
constexpr size_t O_WSUM = 3 * ND;
constexpr size_t O_H1   = 4 * ND;
constexpr size_t O_HHI  = 5 * ND;            // ND bf16 = ND/2 floats
constexpr size_t O_HLO  = 5 * ND + ND / 2;
constexpr size_t O_SBHI = 6 * ND;
constexpr size_t O_SBLO = 6 * ND + ND / 2;
constexpr size_t O_DEN    = 7 * ND;                      // NN floats
constexpr size_t O_DEG    = AL16(O_DEN + NN);            // NN ints
constexpr size_t O_ROWPTR = AL16(O_DEG + NN);            // NN+1 ints
constexpr size_t O_WPOS   = AL16(O_ROWPTR + NN + 1);     // NN ints
constexpr size_t O_CSRS   = AL16(O_WPOS + NN);           // NE ints
constexpr size_t O_CSRE   = AL16(O_CSRS + NE);           // NE ints
constexpr size_t O_WSP    = AL16(O_CSRE + NE);           // 8 x 16384 bf16
constexpr size_t SCRATCH  = O_WSP + 65536 + 64;

// K-chunked GEMM smem (bytes), chunk K=64:
constexpr int LDA  = 144;
constexpr int LDBT = 272;
constexpr int LDBN = 144;
constexpr int A_HI = 0;
constexpr int A_LO = A_HI + 128 * LDA;       // 18432
constexpr int B_HI = A_LO + 128 * LDA;       // 36864
constexpr int B_LO = B_HI + 128 * LDBN;      // 55296
constexpr int GEMM_SMEM = B_LO + 128 * LDBN; // 73728 -> 2 CTAs/SM
}  // namespace

__device__ __align__(256) float g_scratch[SCRATCH];

// ---------------------------------------------------------------------------
// helpers
// ---------------------------------------------------------------------------
__device__ __forceinline__ uint32_t smem_u32(const void* p) {
    uint32_t a;
    asm("{ .reg .u64 t; cvta.to.shared.u64 t, %1; cvt.u32.u64 %0, t; }" : "=r"(a) : "l"(p));
    return a;
}
__device__ __forceinline__ void cpasync16(uint32_t saddr, const void* g, uint32_t srcsz) {
    asm volatile("cp.async.cg.shared.global [%0], [%1], 16, %2;"
                 :: "r"(saddr), "l"(g), "r"(srcsz) : "memory");
}
__device__ __forceinline__ void ldsm_x4(uint32_t* r, uint32_t addr) {
    asm volatile("ldmatrix.sync.aligned.m8n8.x4.shared.b16 {%0,%1,%2,%3}, [%4];"
                 : "=r"(r[0]), "=r"(r[1]), "=r"(r[2]), "=r"(r[3]) : "r"(addr));
}
__device__ __forceinline__ void ldsm_x4t(uint32_t* r, uint32_t addr) {
    asm volatile("ldmatrix.sync.aligned.m8n8.x4.trans.shared.b16 {%0,%1,%2,%3}, [%4];"
                 : "=r"(r[0]), "=r"(r[1]), "=r"(r[2]), "=r"(r[3]) : "r"(addr));
}
__device__ __forceinline__ void mma_bf16(float* d, const uint32_t* a, const uint32_t* b) {
    asm volatile("mma.sync.aligned.m16n8k16.row.col.f32.bf16.bf16.f32 "
                 "{%0,%1,%2,%3}, {%4,%5,%6,%7}, {%8,%9}, {%0,%1,%2,%3};"
                 : "+f"(d[0]), "+f"(d[1]), "+f"(d[2]), "+f"(d[3])
                 : "r"(a[0]), "r"(a[1]), "r"(a[2]), "r"(a[3]), "r"(b[0]), "r"(b[1]));
}
__device__ __forceinline__ float lrelu(float v) { return v >= 0.f ? v : v * NEG_SLOPE; }

__device__ __forceinline__ void split2(float x, float y,
                                       __nv_bfloat162& hi, __nv_bfloat162& lo) {
    hi = __float22bfloat162_rn(make_float2(x, y));
    float2 f = __bfloat1622float2(hi);
    lo = __float22bfloat162_rn(make_float2(x - f.x, y - f.y));
}

// ---------------------------------------------------------------------------
// K-chunked GEMM body, cp.async fill from pre-split bf16 operands.
// wkn=1: W stored [k][n] (C=A@W).  wkn=0: W stored [n][k] (C=A@W^T).
// FIN: epilogue out = lrelu(selfm + (wsumh + acc)/max(denom,1e-30)); if
// outhi != nullptr also emits hi/lo bf16 of the result (next layer's A).
// ---------------------------------------------------------------------------
template <bool FIN>
__device__ __forceinline__ void gemm_body(
    const __nv_bfloat16* __restrict__ Ahi, const __nv_bfloat16* __restrict__ Alo,
    const __nv_bfloat16* __restrict__ Bhi, const __nv_bfloat16* __restrict__ Blo,
    const float* __restrict__ bias, float* __restrict__ C, int wkn, int M,
    const float* __restrict__ wsumh, const float* __restrict__ denom,
    const float* __restrict__ selfm,
    __nv_bfloat16* __restrict__ outhi, __nv_bfloat16* __restrict__ outlo,
    char* smem)
{
    const uint32_t sb = smem_u32(smem);
    const int tid = threadIdx.x, wid = tid >> 5, lane = tid & 31;
    const int row0 = blockIdx.x * 128;
    const int mw = (wid & 3) * 32, nw = (wid >> 2) * 64;

    const uint32_t a_off  = (uint32_t)((mw + (lane & 15)) * LDA + ((lane >> 4) << 4));
    const uint32_t bt_off = (uint32_t)((((lane >> 3) & 1) * 8 + (lane & 7)) * LDBT
                                       + (nw + ((lane >> 4) << 3)) * 2);
    const uint32_t bn_off = (uint32_t)((nw + ((lane >> 4) << 3) + (lane & 7)) * LDBN
                                       + ((lane >> 3) & 1) * 16);

    float acc[2][8][4];
#pragma unroll
    for (int mt = 0; mt < 2; ++mt)
#pragma unroll
        for (int nt = 0; nt < 8; ++nt)
#pragma unroll
            for (int j = 0; j < 4; ++j) acc[mt][nt][j] = 0.f;

#pragma unroll
    for (int c = 0; c < 2; ++c) {
        __syncthreads();   // protect smem reuse from previous chunk's mma

        // --- A chunk ---
        {
            const int r  = tid >> 1;
            const int j0 = (tid & 1) * 4;
            const bool valid = (row0 + r) < M;
            const uint32_t ssz = valid ? 16u : 0u;
            const size_t grow = valid ? (size_t)(row0 + r) : 0;
            const char* gH = (const char*)Ahi + grow * 256 + c * 128 + j0 * 16;
            const char* gL = (const char*)Alo + grow * 256 + c * 128 + j0 * 16;
            const uint32_t sH = sb + A_HI + r * LDA + j0 * 16;
            const uint32_t sL = sb + A_LO + r * LDA + j0 * 16;
#pragma unroll
            for (int i = 0; i < 4; ++i) {
                cpasync16(sH + i * 16, gH + i * 16, ssz);
                cpasync16(sL + i * 16, gL + i * 16, ssz);
            }
        }
        // --- B chunk ---
        if (wkn) {   // [k][n]: 64 k-rows of this chunk, 256B per row
            const int kr = tid >> 2;
            const int j0 = (tid & 3) * 4;
            const char* gH = (const char*)Bhi + (size_t)(c * 64 + kr) * 256 + j0 * 16;
            const char* gL = (const char*)Blo + (size_t)(c * 64 + kr) * 256 + j0 * 16;
            const uint32_t sH = sb + B_HI + kr * LDBT + j0 * 16;
            const uint32_t sL = sb + B_LO + kr * LDBT + j0 * 16;
#pragma unroll
            for (int i = 0; i < 4; ++i) {
                cpasync16(sH + i * 16, gH + i * 16, 16u);
                cpasync16(sL + i * 16, gL + i * 16, 16u);
            }
        } else {     // [n][k]: 128 n-rows, cols chunk
            const int nr = tid >> 1;
            const int j0 = (tid & 1) * 4;
            const char* gH = (const char*)Bhi + (size_t)nr * 256 + c * 128 + j0 * 16;
            const char* gL = (const char*)Blo + (size_t)nr * 256 + c * 128 + j0 * 16;
            const uint32_t sH = sb + B_HI + nr * LDBN + j0 * 16;
            const uint32_t sL = sb + B_LO + nr * LDBN + j0 * 16;
#pragma unroll
            for (int i = 0; i < 4; ++i) {
                cpasync16(sH + i * 16, gH + i * 16, 16u);
                cpasync16(sL + i * 16, gL + i * 16, 16u);
            }
        }
        asm volatile("cp.async.commit_group;" ::: "memory");
        asm volatile("cp.async.wait_group 0;" ::: "memory");
        __syncthreads();

        // --- MMA: 3 groups (hh, hl, lh) x 4 k16-steps ---
#pragma unroll
        for (int g = 0; g < 3; ++g) {
            const uint32_t abase = sb + (g == 2 ? A_LO : A_HI);
            const uint32_t bbase = sb + (g == 1 ? B_LO : B_HI);
#pragma unroll
            for (int kk = 0; kk < 4; ++kk) {
                uint32_t a0[4], a1[4];
                ldsm_x4(a0, abase + a_off + kk * 32);
                ldsm_x4(a1, abase + a_off + 16 * LDA + kk * 32);
#pragma unroll
                for (int p = 0; p < 4; ++p) {
                    uint32_t b4[4];
                    if (wkn)
                        ldsm_x4t(b4, bbase + bt_off + (uint32_t)(kk * 16 * LDBT + p * 32));
                    else
                        ldsm_x4(b4, bbase + bn_off + (uint32_t)(p * 16 * LDBN + kk * 32));
                    mma_bf16(acc[0][2 * p],     a0, b4);
                    mma_bf16(acc[0][2 * p + 1], a0, b4 + 2);
                    mma_bf16(acc[1][2 * p],     a1, b4);
                    mma_bf16(acc[1][2 * p + 1], a1, b4 + 2);
                }
            }
        }
    }

    // --- epilogue ---
    const int rq = lane >> 2, c2 = (lane & 3) * 2;
    if (!FIN) {
#pragma unroll
        for (int mt = 0; mt < 2; ++mt) {
            const int r0 = row0 + mw + mt * 16 + rq;
#pragma unroll
            for (int nt = 0; nt < 8; ++nt) {
                const int col = nw + nt * 8 + c2;
                const float bx = bias ? __ldg(bias + col) : 0.f;
                const float by = bias ? __ldg(bias + col + 1) : 0.f;
                if (r0 < M)
                    *reinterpret_cast<float2*>(C + (size_t)r0 * 128 + col) =
                        make_float2(acc[mt][nt][0] + bx, acc[mt][nt][1] + by);
                if (r0 + 8 < M)
                    *reinterpret_cast<float2*>(C + (size_t)(r0 + 8) * 128 + col) =
                        make_float2(acc[mt][nt][2] + bx, acc[mt][nt][3] + by);
            }
        }
    } else {
#pragma unroll
        for (int mt = 0; mt < 2; ++mt) {
            const int rA = row0 + mw + mt * 16 + rq;
            const int rB = rA + 8;
            float invA = 0.f, invB = 0.f;
            if (rA < M) invA = 1.0f / fmaxf(__ldg(denom + rA), 1e-30f);
            if (rB < M) invB = 1.0f / fmaxf(__ldg(denom + rB), 1e-30f);
#pragma unroll
            for (int nt = 0; nt < 8; ++nt) {
                const int col = nw + nt * 8 + c2;
                if (rA < M) {
                    float2 ws = __ldg(reinterpret_cast<const float2*>(wsumh + (size_t)rA * 128 + col));
                    float2 sm = __ldg(reinterpret_cast<const float2*>(selfm + (size_t)rA * 128 + col));
                    float vx = lrelu(sm.x + (ws.x + acc[mt][nt][0]) * invA);
                    float vy = lrelu(sm.y + (ws.y + acc[mt][nt][1]) * invA);
                    *reinterpret_cast<float2*>(C + (size_t)rA * 128 + col) = make_float2(vx, vy);
                    if (outhi) {
                        __nv_bfloat162 hi, lo;
                        split2(vx, vy, hi, lo);
                        *reinterpret_cast<__nv_bfloat162*>(outhi + (size_t)rA * 128 + col) = hi;
                        *reinterpret_cast<__nv_bfloat162*>(outlo + (size_t)rA * 128 + col) = lo;
                    }
                }
                if (rB < M) {
                    float2 ws = __ldg(reinterpret_cast<const float2*>(wsumh + (size_t)rB * 128 + col));
                    float2 sm = __ldg(reinterpret_cast<const float2*>(selfm + (size_t)rB * 128 + col));
                    float vx = lrelu(sm.x + (ws.x + acc[mt][nt][2]) * invB);
                    float vy = lrelu(sm.y + (ws.y + acc[mt][nt][3]) * invB);
                    *reinterpret_cast<float2*>(C + (size_t)rB * 128 + col) = make_float2(vx, vy);
                    if (outhi) {
                        __nv_bfloat162 hi, lo;
                        split2(vx, vy, hi, lo);
                        *reinterpret_cast<__nv_bfloat162*>(outhi + (size_t)rB * 128 + col) = hi;
                        *reinterpret_cast<__nv_bfloat162*>(outlo + (size_t)rB * 128 + col) = lo;
                    }
                }
            }
        }
    }
}

// batched GEMM: gridDim.y selects (B, bias, C, wkn); all slices share A.
__global__ __launch_bounds__(256, 2)
void tc_gemm3(const __nv_bfloat16* __restrict__ Ahi, const __nv_bfloat16* __restrict__ Alo,
              const __nv_bfloat16* __restrict__ w1h, const __nv_bfloat16* __restrict__ w1l,
              const __nv_bfloat16* __restrict__ w2h, const __nv_bfloat16* __restrict__ w2l,
              const float* __restrict__ b0, const float* __restrict__ b2,
              float* __restrict__ C0, float* __restrict__ C1, float* __restrict__ C2,
              int M)
{
    extern __shared__ char smem[];
    const int y = blockIdx.y;
    const __nv_bfloat16* Bh = (y == 2) ? w2h : w1h;
    const __nv_bfloat16* Bl = (y == 2) ? w2l : w1l;
    const float* b = (y == 0) ? b0 : (y == 1) ? nullptr : b2;
    float*       C = (y == 0) ? C0 : (y == 1) ? C1 : C2;
    const int wkn = (y == 1) ? 0 : 1;
    gemm_body<false>(Ahi, Alo, Bh, Bl, b, C, wkn, M,
                     nullptr, nullptr, nullptr, nullptr, nullptr, smem);
}

// single GEMM with fused finalize epilogue
__global__ __launch_bounds__(256, 2)
void tc_gemm_fin(const __nv_bfloat16* __restrict__ Ahi, const __nv_bfloat16* __restrict__ Alo,
                 const __nv_bfloat16* __restrict__ Bhi, const __nv_bfloat16* __restrict__ Blo,
                 float* __restrict__ out,
                 const float* __restrict__ wsumh, const float* __restrict__ denom,
                 const float* __restrict__ selfm,
                 __nv_bfloat16* __restrict__ outhi, __nv_bfloat16* __restrict__ outlo, int M)
{
    extern __shared__ char smem[];
    gemm_body<true>(Ahi, Alo, Bhi, Blo, nullptr, out, 1, M,
                    wsumh, denom, selfm, outhi, outlo, smem);
}

// ---------------------------------------------------------------------------
// split kernels
// ---------------------------------------------------------------------------
__global__ void hsplit_kernel(const float* __restrict__ x,
                              __nv_bfloat16* __restrict__ hi, __nv_bfloat16* __restrict__ lo)
{
    size_t i = ((size_t)blockIdx.x * blockDim.x + threadIdx.x) * 2;
    if (i >= ND) return;
    float2 v = *reinterpret_cast<const float2*>(x + i);
    __nv_bfloat162 h2, l2;
    split2(v.x, v.y, h2, l2);
    *reinterpret_cast<__nv_bfloat162*>(hi + i) = h2;
    *reinterpret_cast<__nv_bfloat162*>(lo + i) = l2;
}

// split W1/W2 for BOTH layers in one launch (hoisted out of the layer loop)
__global__ void wsplit_all(const float* __restrict__ W1a, const float* __restrict__ W2a,
                           const float* __restrict__ W1b, const float* __restrict__ W2b,
                           __nv_bfloat16* __restrict__ wsp)
{
    int i = (blockIdx.x * blockDim.x + threadIdx.x) * 2;
    if (i >= 16384) return;
    const float* Ws[4] = {W1a, W2a, W1b, W2b};
#pragma unroll
    for (int k = 0; k < 4; ++k) {
        float2 v = *reinterpret_cast<const float2*>(Ws[k] + i);
        __nv_bfloat162 h2, l2;
        split2(v.x, v.y, h2, l2);
        // layout: [w1h_l0, w1l_l0, w2h_l0, w2l_l0, w1h_l1, w1l_l1, w2h_l1, w2l_l1]
        __nv_bfloat16* hi = wsp + ((size_t)(k >> 1) * 4 + (k & 1) * 2) * 16384;
        __nv_bfloat16* lo = hi + 16384;
        *reinterpret_cast<__nv_bfloat162*>(hi + i) = h2;
        *reinterpret_cast<__nv_bfloat162*>(lo + i) = l2;
    }
}

// ---------------------------------------------------------------------------
// CSR build (once; graph shared by both layers)
// ---------------------------------------------------------------------------
__global__ void zero_int_kernel(int* p, int n)
{
    int i = blockIdx.x * blockDim.x + threadIdx.x;
    if (i < n) p[i] = 0;
}

__global__ void deg_kernel(const int* __restrict__ dst, int* __restrict__ deg)
{
    int e = blockIdx.x * blockDim.x + threadIdx.x;
    if (e < NE) atomicAdd(deg + dst[e], 1);
}

__global__ __launch_bounds__(1024) void scan_kernel(const int* __restrict__ deg,
                                                    int* __restrict__ rowptr,
                                                    int* __restrict__ wpos)
{
    __shared__ int warpsum[32];
    __shared__ int carry_s;
    const int tid = threadIdx.x, lane = tid & 31, wid = tid >> 5;
    if (tid == 0) { carry_s = 0; rowptr[0] = 0; }
    __syncthreads();
    for (int base = 0; base < NN; base += 1024) {
        int i = base + tid;
        int v = (i < NN) ? deg[i] : 0;
        int x = v;
#pragma unroll
        for (int o = 1; o < 32; o <<= 1) {
            int y = __shfl_up_sync(0xffffffffu, x, o);
            if (lane >= o) x += y;
        }
        if (lane == 31) warpsum[wid] = x;
        __syncthreads();
        if (wid == 0) {
            int s = warpsum[lane];
#pragma unroll
            for (int o = 1; o < 32; o <<= 1) {
                int y = __shfl_up_sync(0xffffffffu, s, o);
                if (lane >= o) s += y;
            }
            warpsum[lane] = s;
        }
        __syncthreads();
        int incl = x + (wid > 0 ? warpsum[wid - 1] : 0) + carry_s;
        if (i < NN) { rowptr[i + 1] = incl; wpos[i] = incl - v; }
        __syncthreads();
        if (tid == 1023) carry_s = incl;
        __syncthreads();
    }
}

__global__ void csr_scatter(const int* __restrict__ src, const int* __restrict__ dst,
                            int* __restrict__ wpos,
                            int* __restrict__ csr_src, int* __restrict__ csr_e)
{
    int e = blockIdx.x * blockDim.x + threadIdx.x;
    if (e >= NE) return;
    int d = __ldg(dst + e);
    int p = atomicAdd(wpos + d, 1);
    csr_src[p] = __ldg(src + e);
    csr_e[p]   = e;
}

// ---------------------------------------------------------------------------
// aggregation: one warp per dst node, 4-way interleaved chains;
// sbuf emitted directly as bf16 hi/lo (A-operand of the fin GEMM).
// ---------------------------------------------------------------------------
__global__ __launch_bounds__(256) void agg_kernel(
    const float* __restrict__ h, const float* __restrict__ hW1,
    const float* __restrict__ g, const float* __restrict__ ef,
    const int* __restrict__ rowptr, const int* __restrict__ csr_src,
    const int* __restrict__ csr_e,
    float* __restrict__ denom, float* __restrict__ wsumh,
    __nv_bfloat16* __restrict__ sbhi, __nv_bfloat16* __restrict__ sblo)
{
    const int n = blockIdx.x * 8 + (threadIdx.x >> 5);
    if (n >= NN) return;
    const int lane = threadIdx.x & 31;
    const int beg = __ldg(rowptr + n), end = __ldg(rowptr + n + 1);

    float4 ah = make_float4(0.f, 0.f, 0.f, 0.f);
    float4 ae = make_float4(0.f, 0.f, 0.f, 0.f);
    float den = 0.f;

    if (beg < end) {
        const float4 hd = __ldg(reinterpret_cast<const float4*>(h) + n * 32 + lane);
        const float4 gd = __ldg(reinterpret_cast<const float4*>(g) + n * 32 + lane);

        int i = beg;
        for (; i + 3 < end; i += 4) {
            float4 hw[4], ev[4];
#pragma unroll
            for (int j = 0; j < 4; ++j) {
                const int s = __ldg(csr_src + i + j);
                const int e = __ldg(csr_e + i + j);
                hw[j] = __ldg(reinterpret_cast<const float4*>(hW1) + (size_t)s * 32 + lane);
                ev[j] = __ldg(reinterpret_cast<const float4*>(ef)  + (size_t)e * 32 + lane);
            }
            float p[4];
#pragma unroll
            for (int j = 0; j < 4; ++j)
                p[j] = hd.x * hw[j].x + hd.y * hw[j].y + hd.z * hw[j].z + hd.w * hw[j].w
                     + gd.x * ev[j].x + gd.y * ev[j].y + gd.z * ev[j].z + gd.w * ev[j].w;
#pragma unroll
            for (int o = 16; o > 0; o >>= 1) {
#pragma unroll
                for (int j = 0; j < 4; ++j)
                    p[j] += __shfl_xor_sync(0xffffffffu, p[j], o);
            }
#pragma unroll
            for (int j = 0; j < 4; ++j) {
                const float w = __expf(p[j]);
                ah.x += w * hw[j].x; ah.y += w * hw[j].y;
                ah.z += w * hw[j].z; ah.w += w * hw[j].w;
                ae.x += w * ev[j].x; ae.y += w * ev[j].y;
                ae.z += w * ev[j].z; ae.w += w * ev[j].w;
                den += w;
            }
        }
        for (; i < end; ++i) {
            const int s0 = __ldg(csr_src + i), e0 = __ldg(csr_e + i);
            const float4 hw0 = __ldg(reinterpret_cast<const float4*>(hW1) + (size_t)s0 * 32 + lane);
            const float4 ev0 = __ldg(reinterpret_cast<const float4*>(ef)  + (size_t)e0 * 32 + lane);
            float p0 = hd.x * hw0.x + hd.y * hw0.y + hd.z * hw0.z + hd.w * hw0.w
                     + gd.x * ev0.x + gd.y * ev0.y + gd.z * ev0.z + gd.w * ev0.w;
#pragma unroll
            for (int o = 16; o > 0; o >>= 1) p0 += __shfl_xor_sync(0xffffffffu, p0, o);
            const float w0 = __expf(p0);
            ah.x += w0 * hw0.x; ah.y += w0 * hw0.y; ah.z += w0 * hw0.z; ah.w += w0 * hw0.w;
            ae.x += w0 * ev0.x; ae.y += w0 * ev0.y; ae.z += w0 * ev0.z; ae.w += w0 * ev0.w;
            den += w0;
        }
    }

    reinterpret_cast<float4*>(wsumh)[n * 32 + lane] = ah;
    {
        const size_t idx = (size_t)n * 128 + lane * 4;
        __nv_bfloat162 h01, l01, h23, l23;
        split2(ae.x, ae.y, h01, l01);
        split2(ae.z, ae.w, h23, l23);
        *reinterpret_cast<__nv_bfloat162*>(sbhi + idx)     = h01;
        *reinterpret_cast<__nv_bfloat162*>(sbhi + idx + 2) = h23;
        *reinterpret_cast<__nv_bfloat162*>(sblo + idx)     = l01;
        *reinterpret_cast<__nv_bfloat162*>(sblo + idx + 2) = l23;
    }
    if (lane == 0) denom[n] = den;
}

// ---------------------------------------------------------------------------
// fixup: for the rare deg==0 nodes, out = lrelu(h@W3 + b3).  warp/node.
// ---------------------------------------------------------------------------
__global__ __launch_bounds__(256) void fixup_iso(
    const float* __restrict__ h, const float* __restrict__ W3,
    const float* __restrict__ b3, const int* __restrict__ rowptr,
    float* __restrict__ out,
    __nv_bfloat16* __restrict__ outhi, __nv_bfloat16* __restrict__ outlo)
{
    int n = blockIdx.x * 8 + (threadIdx.x >> 5);
    if (n >= NN) return;
    if (__ldg(rowptr + n + 1) != __ldg(rowptr + n)) return;
    int lane = threadIdx.x & 31;
    int c0 = lane * 4;

    float acc0 = __ldg(b3 + c0), acc1 = __ldg(b3 + c0 + 1);
    float acc2 = __ldg(b3 + c0 + 2), acc3 = __ldg(b3 + c0 + 3);
    for (int k = 0; k < 128; ++k) {
        float hv = __ldg(h + (size_t)n * 128 + k);
        const float* wr = W3 + (size_t)k * 128 + c0;
        acc0 += hv * __ldg(wr);
        acc1 += hv * __ldg(wr + 1);
        acc2 += hv * __ldg(wr + 2);
        acc3 += hv * __ldg(wr + 3);
    }
    float4 r = make_float4(lrelu(acc0), lrelu(acc1), lrelu(acc2), lrelu(acc3));
    *reinterpret_cast<float4*>(out + (size_t)n * 128 + c0) = r;
    if (outhi) {
        __nv_bfloat162 h01, l01, h23, l23;
        split2(r.x, r.y, h01, l01);
        split2(r.z, r.w, h23, l23);
        const size_t idx = (size_t)n * 128 + c0;
        *reinterpret_cast<__nv_bfloat162*>(outhi + idx)     = h01;
        *reinterpret_cast<__nv_bfloat162*>(outhi + idx + 2) = h23;
        *reinterpret_cast<__nv_bfloat162*>(outlo + idx)     = l01;
        *reinterpret_cast<__nv_bfloat162*>(outlo + idx + 2) = l23;
    }
}

// ---------------------------------------------------------------------------
// launch
// ---------------------------------------------------------------------------
extern "C" void kernel_launch(void* const* d_in, const int* in_sizes, int n_in,
                              void* d_out, int out_size)
{
    const float* node = (const float*)d_in[0];
    const float* ef   = (const float*)d_in[1];
    const int*   src  = (const int*)d_in[2];
    const int*   dst  = (const int*)d_in[3];
    const float* W1[2] = {(const float*)d_in[4],  (const float*)d_in[10]};
    const float* B1[2] = {(const float*)d_in[5],  (const float*)d_in[11]};
    const float* W2[2] = {(const float*)d_in[6],  (const float*)d_in[12]};
    const float* B2[2] = {(const float*)d_in[7],  (const float*)d_in[13]};
    const float* W3[2] = {(const float*)d_in[8],  (const float*)d_in[14]};
    const float* B3[2] = {(const float*)d_in[9],  (const float*)d_in[15]};

    float* base = nullptr;
    cudaGetSymbolAddress((void**)&base, g_scratch);

    float* hW1    = base + O_HW1;
    float* g      = base + O_G;
    float* selfm  = base + O_SELF;
    float* wsumh  = base + O_WSUM;
    float* h1     = base + O_H1;
    __nv_bfloat16* hhi  = (__nv_bfloat16*)(base + O_HHI);
    __nv_bfloat16* hlo  = (__nv_bfloat16*)(base + O_HLO);
    __nv_bfloat16* sbhi = (__nv_bfloat16*)(base + O_SBHI);
    __nv_bfloat16* sblo = (__nv_bfloat16*)(base + O_SBLO);
    float* denom  = base + O_DEN;
    int*   deg    = (int*)(base + O_DEG);
    int*   rowptr = (int*)(base + O_ROWPTR);
    int*   wpos   = (int*)(base + O_WPOS);
    int*   csrs   = (int*)(base + O_CSRS);
    int*   csre   = (int*)(base + O_CSRE);
    __nv_bfloat16* wsp = (__nv_bfloat16*)(base + O_WSP);
    // per layer l: w1h = wsp + l*4*16384, w1l = +16384, w2h = +32768, w2l = +49152

    cudaFuncSetAttribute(tc_gemm3,    cudaFuncAttributeMaxDynamicSharedMemorySize, GEMM_SMEM);
    cudaFuncSetAttribute(tc_gemm_fin, cudaFuncAttributeMaxDynamicSharedMemorySize, GEMM_SMEM);

    // ---- CSR build (once) ----
    zero_int_kernel<<<(NN + 255) / 256, 256>>>(deg, NN);
    deg_kernel<<<(NE + 255) / 256, 256>>>(dst, deg);
    scan_kernel<<<1, 1024>>>(deg, rowptr, wpos);
    csr_scatter<<<(NE + 255) / 256, 256>>>(src, dst, wpos, csrs, csre);

    // ---- splits hoisted out of the loop ----
    hsplit_kernel<<<(int)((ND / 2 + 255) / 256), 256>>>(node, hhi, hlo);
    wsplit_all<<<32, 256>>>(W1[0], W2[0], W1[1], W2[1], wsp);

    const int gemmGrid = (NN + 127) / 128;   // 391
    const int nodeGrid = (NN + 7) / 8;       // 6250

    const float* h = node;
    float* out_l[2] = {h1, (float*)d_out};

    for (int l = 0; l < 2; ++l) {
        __nv_bfloat16* w1h = wsp + (size_t)l * 4 * 16384;
        __nv_bfloat16* w1l = w1h + 16384;
        __nv_bfloat16* w2h = w1l + 16384;
        __nv_bfloat16* w2l = w2h + 16384;

        // y=0: hW1 = h@W1+b1;  y=1: g = h@W1^T;  y=2: selfm = h@W2+b2
        tc_gemm3<<<dim3(gemmGrid, 3), 256, GEMM_SMEM>>>(
            hhi, hlo, w1h, w1l, w2h, w2l, B1[l], B2[l],
            hW1, g, selfm, NN);

        agg_kernel<<<nodeGrid, 256>>>(h, hW1, g, ef, rowptr, csrs, csre,
                                      denom, wsumh, sbhi, sblo);

        // out = lrelu(selfm + (wsumh + sbuf@W1)/denom); layer0 also emits
        // hi/lo split of h1 (A operand for layer1).
        tc_gemm_fin<<<gemmGrid, 256, GEMM_SMEM>>>(
            sbhi, sblo, w1h, w1l, out_l[l], wsumh, denom, selfm,
            (l == 0) ? hhi : nullptr, (l == 0) ? hlo : nullptr, NN);

        fixup_iso<<<nodeGrid, 256>>>(h, W3[l], B3[l], rowptr, out_l[l],
                                     (l == 0) ? hhi : nullptr,
                                     (l == 0) ? hlo : nullptr);

        h = h1;
    }
}